// round 17
// baseline (speedup 1.0000x reference)
#include <cuda_runtime.h>
#include <cuda_fp16.h>
#include <math.h>
#include <stdint.h>

#define BATCH 8
#define SEQ   2048
#define DIM   768
#define MTOT  (BATCH*SEQ)

// ---------------- static device scratch ----------------
__device__ __half g_xh [(size_t)MTOT*DIM];
__device__ __half g_WqT[DIM*DIM];
__device__ __half g_WkT[DIM*DIM];
__device__ __half g_Wvh[DIM*DIM];
__device__ __half g_NT [DIM*DIM];
__device__ __half g_G  [(size_t)MTOT*DIM];
__device__ __half g_Vth[(size_t)DIM*MTOT];
__device__ __half g_Ph [(size_t)BATCH*SEQ*SEQ];
__device__ float  g_rowsum[MTOT];

// ---- sync state ----
__device__ __align__(16) int g_sync[640];
#define SY_QHEAD 0
#define SY_NCNT  1      // N tiles done, target 36
#define SY_WT    2      // Wq/Wk transpose conv tiles, target 72
#define SY_WV    3      // Wv conv tiles, target 36
#define SY_RS    4      // rowsum zero tile, target 1
#define SY_VT    8      // [nxc*8 + z] -> 48 entries, target 16
#define SY_G     64     // [global row-block 0..127], target 6
#define SY_X     192    // [x slice 0..127], target 6
#define SY_S     320    // [z*16 + qb], target 16

// ---- tile queue layout ----
#define NT_C0  109                     // 72 WT + 36 Wv + 1 rowsum-zero
#define NT_N   36
#define NT_XC  768                     // x conversion, 6 tiles per 128-row slice
#define NT_VT  768
#define NT_G   768
#define NT_S   2048
#define NT_AV  768
#define T0_N   (NT_C0)                 // 109
#define T0_XC  (T0_N + NT_N)           // 145
#define T0_VT  (T0_XC + NT_XC)         // 913
#define T0_G   (T0_VT + NT_VT)         // 1681
#define T0_S   (T0_G + NT_G)           // 2449
#define T0_AV  (T0_S + NT_S)           // 4497
#define NTILES (T0_AV + NT_AV)         // 5265
#define GRID_P 296

// ---------------- tiling: 128x128x64, 3-stage, 2 CTAs/SM ----------------
#define BM 128
#define BN 128
#define BK 64
#define ROWB 144
#define TILE_A (128*ROWB)
#define TILE_B (128*ROWB)
#define WSTAGE (TILE_A + TILE_B)
#define SMEM_G (3*WSTAGE)              // 110592 B

// ---------------- PTX helpers ----------------
__device__ __forceinline__ uint32_t smem_u32(const void* p) {
    uint32_t a;
    asm("{ .reg .u64 t; cvta.to.shared.u64 t, %1; cvt.u32.u64 %0, t; }" : "=r"(a) : "l"(p));
    return a;
}
__device__ __forceinline__ void cp_async16(uint32_t saddr, const void* gaddr) {
    asm volatile("cp.async.cg.shared.global [%0], [%1], 16;" :: "r"(saddr), "l"(gaddr));
}
__device__ __forceinline__ void cp_commit() {
    asm volatile("cp.async.commit_group;" ::: "memory");
}
template<int N> __device__ __forceinline__ void cp_wait() {
    asm volatile("cp.async.wait_group %0;" :: "n"(N) : "memory");
}
__device__ __forceinline__ void ldsm4(uint32_t* r, uint32_t addr) {
    asm volatile("ldmatrix.sync.aligned.m8n8.x4.shared.b16 {%0,%1,%2,%3}, [%4];"
                 : "=r"(r[0]), "=r"(r[1]), "=r"(r[2]), "=r"(r[3]) : "r"(addr));
}
__device__ __forceinline__ void mma16816(float* c, const uint32_t* a, const uint32_t* b) {
    asm volatile(
        "mma.sync.aligned.m16n8k16.row.col.f32.f16.f16.f32 "
        "{%0,%1,%2,%3}, {%4,%5,%6,%7}, {%8,%9}, {%0,%1,%2,%3};"
        : "+f"(c[0]), "+f"(c[1]), "+f"(c[2]), "+f"(c[3])
        : "r"(a[0]), "r"(a[1]), "r"(a[2]), "r"(a[3]), "r"(b[0]), "r"(b[1]));
}

// ======= shared GEMM core: 128x128x64 tile, 3-stage, single-buffered frags =======
struct GemmCore {
    const __half* pA;
    const __half* pB;
    int ldaStep, ldbStep;
    uint32_t sA0, sB0;
    uint32_t aOff, bOff;

    __device__ __forceinline__ void init(const __half* AB, const __half* BB,
                                         int lda, int ldb, int rowBase, int colBase,
                                         int tid, int lane, int wm, int wn)
    {
        const int tr = tid >> 3;
        const int tc = tid & 7;
        pA = AB + (long)(rowBase + tr) * lda + tc * 8;
        pB = BB + (long)(colBase + tr) * ldb + tc * 8;
        ldaStep = 32 * lda;
        ldbStep = 32 * ldb;
        sA0 = tr * ROWB + tc * 16;
        sB0 = TILE_A + tr * ROWB + tc * 16;

        const int j = lane >> 3, r = lane & 7;
        aOff = (uint32_t)(wm * 64 + (j & 1) * 8 + r) * ROWB + ((j >> 1) * 8) * 2;
        bOff = (uint32_t)(wn * 32 + (j >> 1) * 8 + r) * ROWB + ((j & 1) * 8) * 2;
    }

    __device__ __forceinline__ void load_stage(uint32_t sbase, int k0)
    {
#pragma unroll
        for (int i = 0; i < 4; i++)
            cp_async16(sbase + sA0 + i * (32 * ROWB), pA + k0 + i * ldaStep);
#pragma unroll
        for (int i = 0; i < 4; i++)
            cp_async16(sbase + sB0 + i * (32 * ROWB), pB + k0 + i * ldbStep);
    }

    __device__ __forceinline__ void run(uint32_t sb, int kTiles, float acc[4][4][4])
    {
#pragma unroll
        for (int s = 0; s < 2; s++) {
            load_stage(sb + s * WSTAGE, s * BK);
            cp_commit();
        }

        uint32_t ah[4][4], bh[4][2];

        for (int kt = 0; kt < kTiles; kt++) {
            cp_wait<1>();
            __syncthreads();

            {
                int ft = kt + 2;
                if (ft < kTiles)
                    load_stage(sb + (ft % 3) * WSTAGE, ft * BK);
                cp_commit();
            }

            const uint32_t stage = sb + (kt % 3) * WSTAGE;

#pragma unroll
            for (int ks = 0; ks < 4; ks++) {
                const uint32_t kb = ks * 32;
#pragma unroll
                for (int mt = 0; mt < 4; mt++)
                    ldsm4(ah[mt], stage + aOff + mt * 16 * ROWB + kb);
#pragma unroll
                for (int p = 0; p < 2; p++) {
                    uint32_t t[4];
                    ldsm4(t, stage + TILE_A + bOff + p * 16 * ROWB + kb);
                    bh[2 * p][0] = t[0]; bh[2 * p][1] = t[1];
                    bh[2 * p + 1][0] = t[2]; bh[2 * p + 1][1] = t[3];
                }
#pragma unroll
                for (int mt = 0; mt < 4; mt++)
#pragma unroll
                    for (int nt = 0; nt < 4; nt++)
                        mma16816(acc[mt][nt], ah[mt], bh[nt]);
            }
        }
    }
};

__device__ __forceinline__ void acc_zero(float acc[4][4][4]) {
#pragma unroll
    for (int a = 0; a < 4; a++)
#pragma unroll
        for (int b = 0; b < 4; b++)
#pragma unroll
            for (int q = 0; q < 4; q++) acc[a][b][q] = 0.f;
}

__device__ __forceinline__ void epilogue_h(float acc[4][4][4], __half* Ch, long ldc,
                                           int mRow0, int nCol0)
{
#pragma unroll
    for (int mt = 0; mt < 4; mt++) {
#pragma unroll
        for (int nt = 0; nt < 4; nt++) {
            float* c = acc[mt][nt];
            long r0 = mRow0 + mt * 16;
            int  cc = nCol0 + nt * 8;
#pragma unroll
            for (int h = 0; h < 2; h++) {
                __half2 hp;
                hp.x = __float2half(c[2 * h]);
                hp.y = __float2half(c[2 * h + 1]);
                *(__half2*)(Ch + (r0 + 8 * h) * ldc + cc) = hp;
            }
        }
    }
}

// wait for up to 3 (counter, target) pairs; tid0 spins, CTA joins at one barrier
__device__ __forceinline__ void dep_wait3(int i0, int t0, int i1, int t1,
                                          int i2, int t2, int tid) {
    if (tid == 0) {
        if (t0) { volatile int* c = &g_sync[i0]; while (*c < t0) __nanosleep(64); }
        if (t1) { volatile int* c = &g_sync[i1]; while (*c < t1) __nanosleep(64); }
        if (t2) { volatile int* c = &g_sync[i2]; while (*c < t2) __nanosleep(64); }
    }
    __syncthreads();
}

__device__ __forceinline__ void dep_signal(int idx, int tid) {
    __threadfence();
    __syncthreads();
    if (tid == 0) atomicAdd(&g_sync[idx], 1);
}

// ================= persistent mega-kernel: conversion + all GEMM phases =================
__global__ void __launch_bounds__(256, 2) mega(
    const float4* __restrict__ xf, const float4* __restrict__ Wq,
    const float4* __restrict__ Wk, const float4* __restrict__ Wv,
    float* __restrict__ out)
{
    extern __shared__ char smem[];
    const uint32_t sb = smem_u32(smem);
    const int tid  = threadIdx.x;
    const int lane = tid & 31;
    const int wid  = tid >> 5;
    const int wm   = wid & 1;
    const int wn   = wid >> 1;
    const float scale = rsqrtf((float)DIM);

    __shared__ int s_t;

    for (;;) {
        __syncthreads();
        if (tid == 0) s_t = atomicAdd(&g_sync[SY_QHEAD], 1);
        __syncthreads();
        const int t = s_t;
        if (t >= NTILES) return;

        if (t < T0_N) {
            // ---- C0: W conversions + rowsum zero (4096 float4 per tile) ----
            if (t < 72) {
                int wsel = t / 36, sub = t % 36;
                const float4* s = wsel ? Wk : Wq;
                __half* d = wsel ? g_WkT : g_WqT;
#pragma unroll
                for (int j = 0; j < 16; j++) {
                    int off = sub * 4096 + tid + j * 256;
                    float4 v = s[off];
                    int row = off / (DIM / 4);
                    int c0  = (off % (DIM / 4)) * 4;
                    d[(c0 + 0) * DIM + row] = __float2half(v.x);
                    d[(c0 + 1) * DIM + row] = __float2half(v.y);
                    d[(c0 + 2) * DIM + row] = __float2half(v.z);
                    d[(c0 + 3) * DIM + row] = __float2half(v.w);
                }
                dep_signal(SY_WT, tid);
            } else if (t < 108) {
                int sub = t - 72;
                __half2* d = (__half2*)g_Wvh;
#pragma unroll
                for (int j = 0; j < 16; j++) {
                    int off = sub * 4096 + tid + j * 256;
                    float4 v = Wv[off];
                    d[2 * off]     = __floats2half2_rn(v.x, v.y);
                    d[2 * off + 1] = __floats2half2_rn(v.z, v.w);
                }
                dep_signal(SY_WV, tid);
            } else {
                // rowsum zero: 4096 float4 = 16384 floats
#pragma unroll
                for (int j = 0; j < 16; j++)
                    ((float4*)g_rowsum)[tid + j * 256] = make_float4(0.f, 0.f, 0.f, 0.f);
                dep_signal(SY_RS, tid);
            }
            continue;
        }

        if (t < T0_XC) {
            // ---- N^T = NT(WkT, WqT) ----
            int i1 = t - T0_N;
            int bx = i1 % 6, by = i1 / 6;
            dep_wait3(SY_WT, 72, 0, 0, 0, 0, tid);
            float acc[4][4][4]; acc_zero(acc);
            GemmCore core;
            core.init(g_WkT, g_WqT, DIM, DIM, by * BM, bx * BN, tid, lane, wm, wn);
            core.run(sb, DIM / BK, acc);
            int mRow0 = by * BM + wm * 64 + (lane >> 2);
            int nCol0 = bx * BN + wn * 32 + 2 * (lane & 3);
            epilogue_h(acc, g_NT, DIM, mRow0, nCol0);
            dep_signal(SY_NCNT, tid);
            continue;
        }

        if (t < T0_VT) {
            // ---- x conversion (slice-major: tile t2 covers rows of slice t2/6) ----
            int t2 = t - T0_XC;
            __half2* d = (__half2*)g_xh;
#pragma unroll
            for (int j = 0; j < 16; j++) {
                int off = t2 * 4096 + tid + j * 256;
                float4 v = xf[off];
                d[2 * off]     = __floats2half2_rn(v.x, v.y);
                d[2 * off + 1] = __floats2half2_rn(v.z, v.w);
            }
            dep_signal(SY_X + t2 / 6, tid);
            continue;
        }

        float acc[4][4][4];
        acc_zero(acc);
        GemmCore core;

        if (t < T0_G) {
            // ---- Vt = NT(Wvh, xh): [DIM, MTOT] ----
            int i2 = t - T0_VT;
            int nx = i2 % 128, my = i2 / 128;
            dep_wait3(SY_WV, 36, SY_X + nx, 6, 0, 0, tid);
            core.init(g_Wvh, g_xh, DIM, DIM, my * BM, nx * BN, tid, lane, wm, wn);
            core.run(sb, DIM / BK, acc);
            int mRow0 = my * BM + wm * 64 + (lane >> 2);
            int nCol0 = nx * BN + wn * 32 + 2 * (lane & 3);
            epilogue_h(acc, g_Vth, MTOT, mRow0, nCol0);
            dep_signal(SY_VT + my * 8 + (nx >> 4), tid);
        }
        else if (t < T0_S) {
            // ---- G = NT(xh, NT): [MTOT, DIM] ----
            int i3 = t - T0_G;
            int nx = i3 % 6, my = i3 / 6;
            dep_wait3(SY_NCNT, NT_N, SY_X + my, 6, 0, 0, tid);
            core.init(g_xh, g_NT, DIM, DIM, my * BM, nx * BN, tid, lane, wm, wn);
            core.run(sb, DIM / BK, acc);
            int mRow0 = my * BM + wm * 64 + (lane >> 2);
            int nCol0 = nx * BN + wn * 32 + 2 * (lane & 3);
            epilogue_h(acc, g_G, DIM, mRow0, nCol0);
            dep_signal(SY_G + my, tid);
        }
        else if (t < T0_AV) {
            // ---- scores: Ph = exp(scale * G@x^T) + row sums ----
            int i4 = t - T0_S;
            int z = i4 >> 8, r = i4 & 255;
            int qb = r >> 4, kb = r & 15;
            dep_wait3(SY_G + z * 16 + qb, 6, SY_X + z * 16 + kb, 6, SY_RS, 1, tid);

            const __half* AB = g_G  + (long)z * SEQ * DIM;
            const __half* BB = g_xh + (long)z * SEQ * DIM;
            core.init(AB, BB, DIM, DIM, qb * BM, kb * BN, tid, lane, wm, wn);
            core.run(sb, DIM / BK, acc);

            __half* Ch = g_Ph + (long)z * SEQ * SEQ;
            int mRow0 = qb * BM + wm * 64 + (lane >> 2);
            int nCol0 = kb * BN + wn * 32 + 2 * (lane & 3);

            float rsum[4][2];
#pragma unroll
            for (int mt = 0; mt < 4; mt++) { rsum[mt][0] = 0.f; rsum[mt][1] = 0.f; }

#pragma unroll
            for (int mt = 0; mt < 4; mt++) {
#pragma unroll
                for (int nt = 0; nt < 4; nt++) {
                    float* c = acc[mt][nt];
                    long r0 = mRow0 + mt * 16;
                    int  cc = nCol0 + nt * 8;
#pragma unroll
                    for (int h = 0; h < 2; h++) {
                        float e0 = __expf(c[2 * h]     * scale);
                        float e1 = __expf(c[2 * h + 1] * scale);
                        rsum[mt][h] += e0 + e1;
                        __half2 hp = __floats2half2_rn(e0, e1);
                        *(__half2*)(Ch + (r0 + 8 * h) * (long)SEQ + cc) = hp;
                    }
                }
            }
#pragma unroll
            for (int mt = 0; mt < 4; mt++) {
#pragma unroll
                for (int h = 0; h < 2; h++) {
                    float p = rsum[mt][h];
                    p += __shfl_xor_sync(0xffffffffu, p, 1);
                    p += __shfl_xor_sync(0xffffffffu, p, 2);
                    if ((lane & 3) == 0) {
                        long row = (long)z * SEQ + mRow0 + mt * 16 + 8 * h;
                        atomicAdd(&g_rowsum[row], p);
                    }
                }
            }
            dep_signal(SY_S + z * 16 + qb, tid);
        }
        else {
            // ---- av: out = (Ph @ Vt^T) / rowsum ----
            int i5 = t - T0_AV;
            int z = i5 / 96, r = i5 % 96;
            int qb = r / 6, nxc = r % 6;
            dep_wait3(SY_S + z * 16 + qb, 16, SY_VT + nxc * 8 + z, 16, 0, 0, tid);

            const __half* AB = g_Ph  + (long)z * SEQ * SEQ;
            const __half* BB = g_Vth + (long)z * SEQ;
            core.init(AB, BB, SEQ, MTOT, qb * BM, nxc * BN, tid, lane, wm, wn);
            core.run(sb, SEQ / BK, acc);

            float* Cff = out + (long)z * SEQ * DIM;
            int mRow0 = qb * BM + wm * 64 + (lane >> 2);
            int nCol0 = nxc * BN + wn * 32 + 2 * (lane & 3);

            float inv[4][2];
#pragma unroll
            for (int mt = 0; mt < 4; mt++)
#pragma unroll
                for (int h = 0; h < 2; h++)
                    inv[mt][h] = 1.0f / g_rowsum[(long)z * SEQ + mRow0 + mt * 16 + 8 * h];

#pragma unroll
            for (int mt = 0; mt < 4; mt++) {
#pragma unroll
                for (int nt = 0; nt < 4; nt++) {
                    float* c = acc[mt][nt];
                    long r0 = mRow0 + mt * 16;
                    int  cc = nCol0 + nt * 8;
                    *(float2*)(Cff + r0 * (long)DIM + cc) =
                        make_float2(c[0] * inv[mt][0], c[1] * inv[mt][0]);
                    *(float2*)(Cff + (r0 + 8) * (long)DIM + cc) =
                        make_float2(c[2] * inv[mt][1], c[3] * inv[mt][1]);
                }
            }
        }
    }
}

// ---------------- tiny init: zero sync state ----------------
__global__ void __launch_bounds__(256) init_sync()
{
    int i = blockIdx.x * 256 + threadIdx.x;
    if (i < 640) g_sync[i] = 0;
}

// ---------------- host launcher ----------------
extern "C" void kernel_launch(void* const* d_in, const int* in_sizes, int n_in,
                              void* d_out, int out_size)
{
    const float* x  = (const float*)d_in[0];
    const float* Wq = (const float*)d_in[1];
    const float* Wk = (const float*)d_in[2];
    const float* Wv = (const float*)d_in[3];
    float* out = (float*)d_out;

    cudaFuncSetAttribute((const void*)mega, cudaFuncAttributeMaxDynamicSharedMemorySize, SMEM_G);

    init_sync<<<3, 256>>>();
    mega<<<GRID_P, 256, SMEM_G>>>((const float4*)x, (const float4*)Wq,
                                  (const float4*)Wk, (const float4*)Wv, out);
}